// round 8
// baseline (speedup 1.0000x reference)
#include <cuda_runtime.h>

#define BATCH   16
#define CIN     64
#define HW      64
#define OC      128
#define NLEAF   16
#define NGATE   15

// Spatial y-tile per CTA: 32 wide x 8 tall. Halo for taps (py,px in [0,2], pad 1):
// x rows [r0-1, r0+8] (10 rows), x cols [c0-1, c0+32] (34 cols).
#define TW 32
#define TH 8
#define SC 34
#define SR 10
#define CH_STRIDE (SR * SC)            // 340
#define SMEM_ELEMS (CIN * CH_STRIDE)   // 21760
#define SMEM_BYTES (SMEM_ELEMS * 4)    // 87040

// Precomputed per-launch (deterministic function of inputs; recomputed every replay).
__device__ float g_coef[OC * NGATE * 4];   // per gate: {c0, ca, cb, cab}, 16B-aligned per oc
__device__ int   g_off[OC * NLEAF];

__device__ __constant__ float OP2POLY[16][4] = {
    {0, 0, 0, 0}, {0, 0, 0, 1}, {0, 1, 0, -1}, {0, 1, 0, 0},
    {0, 0, 1, -1}, {0, 0, 1, 0}, {0, 1, 1, -2}, {0, 1, 1, -1},
    {1, -1, -1, 1}, {1, -1, -1, 2}, {1, 0, -1, 0}, {1, 0, -1, 1},
    {1, -1, 0, 0}, {1, -1, 0, 1}, {1, 0, 0, -1}, {1, 0, 0, 0}
};

// Tiny prep: argmax over 16 ops -> 4 poly coeffs per gate; fold (ci,py,px) into a
// single smem element offset per leaf.
__global__ void prep_kernel(const float* __restrict__ w,
                            const int* __restrict__ ci,
                            const int* __restrict__ px,
                            const int* __restrict__ py) {
    int tid = blockIdx.x * blockDim.x + threadIdx.x;
    if (tid < OC * NGATE) {
        const float* wp = w + tid * 16;
        float best = wp[0];
        int bi = 0;
#pragma unroll
        for (int k = 1; k < 16; k++) {
            float v = wp[k];
            if (v > best) { best = v; bi = k; }  // first-max tiebreak == jnp.argmax
        }
#pragma unroll
        for (int c = 0; c < 4; c++) g_coef[tid * 4 + c] = OP2POLY[bi][c];
    }
    if (tid < OC * NLEAF) {
        g_off[tid] = ci[tid] * CH_STRIDE + py[tid] * SC + px[tid];
    }
}

// Horner-form gate: c0 + ca*a + cb*b + cab*a*b = (cab*a + cb)*b + (ca*a + c0)
// 3 FMA total (was mul + 3 FMA).
__device__ __forceinline__ float gate3(float c0, float ca, float cb, float cab,
                                       float a, float b) {
    float t = fmaf(cab, a, cb);
    float s = fmaf(ca, a, c0);
    return fmaf(t, b, s);
}

__global__ void __launch_bounds__(256, 2)
logic_tree_kernel(const float* __restrict__ x, float* __restrict__ out) {
    extern __shared__ float sm[];

    const int tile = blockIdx.x;        // 0..15: tx in [0,2), ty in [0,8)
    const int b    = blockIdx.y;        // 0..15
    const int tx   = tile & 1;
    const int ty   = tile >> 1;
    const int r0   = ty * TH;
    const int c0   = tx * TW;
    const int tid  = threadIdx.x;

    // Stage all 64 channels of the halo region into smem (zero-fill OOB).
    // 4 threads per channel, 85 contiguous elements each: no div-by-340 in the loop.
    {
        const float* xb = x + (size_t)b * CIN * HW * HW;
        const int c  = tid >> 2;                 // channel 0..63
        const int e0 = (tid & 3) * 85;           // element range [e0, e0+85)
        const float* xc = xb + c * HW * HW;
        float* smc = sm + c * CH_STRIDE;
#pragma unroll 5
        for (int e = e0; e < e0 + 85; e++) {
            int r   = e / SC;                    // small-range div -> mul/shift
            int col = e - r * SC;
            int gr  = r0 - 1 + r;
            int gc  = c0 - 1 + col;
            float v = 0.0f;
            if ((unsigned)gr < HW && (unsigned)gc < HW)
                v = xc[gr * HW + gc];
            smc[e] = v;
        }
    }
    __syncthreads();

    const int w    = tid >> 5;   // warp 0..7
    const int lane = tid & 31;   // y-column within tile -> conflict-free LDS

    for (int oc = w; oc < OC; oc += 8) {
        // Leaf smem indices hoisted: lane folded in once; subrow becomes an
        // immediate offset on the LDS below.
        int idx[NLEAF];
        {
            const int4* op = (const int4*)&g_off[oc * NLEAF];
#pragma unroll
            for (int q = 0; q < 4; q++) {
                int4 o4 = op[q];
                idx[4 * q + 0] = o4.x + lane;
                idx[4 * q + 1] = o4.y + lane;
                idx[4 * q + 2] = o4.z + lane;
                idx[4 * q + 3] = o4.w + lane;
            }
        }

        // Coefficients: 15 gates x float4 (vectorized 128-bit loads, warp-uniform).
        float4 cf[NGATE];
        {
            const float4* cp = (const float4*)&g_coef[oc * NGATE * 4];
#pragma unroll
            for (int k = 0; k < NGATE; k++) cf[k] = cp[k];
        }

        float* outoc = out + (((size_t)b * OC + oc) * 32 + ty * 4) * 32 + tx * 16;

#pragma unroll
        for (int ph = 0; ph < 4; ph++) {
            float prodp = 1.0f;
#pragma unroll
            for (int sub = 0; sub < 2; sub++) {
                const int srow = (ph * 2 + sub) * SC;   // compile-time constant

                float v[16];
#pragma unroll
                for (int n = 0; n < 16; n++) v[n] = sm[idx[n] + srow];

                float u[8];
#pragma unroll
                for (int n = 0; n < 8; n++)
                    u[n] = gate3(cf[n].x, cf[n].y, cf[n].z, cf[n].w,
                                 v[2 * n], v[2 * n + 1]);

                float t[4];
#pragma unroll
                for (int n = 0; n < 4; n++)
                    t[n] = gate3(cf[8 + n].x, cf[8 + n].y, cf[8 + n].z, cf[8 + n].w,
                                 u[2 * n], u[2 * n + 1]);

                float s0 = gate3(cf[12].x, cf[12].y, cf[12].z, cf[12].w, t[0], t[1]);
                float s1 = gate3(cf[13].x, cf[13].y, cf[13].z, cf[13].w, t[2], t[3]);
                float y  = gate3(cf[14].x, cf[14].y, cf[14].z, cf[14].w, s0, s1);

                // prodp *= (1 - y)  as a single FMA
                prodp = fmaf(-prodp, y, prodp);
            }
            // Column pooling: combine neighbor lane (j even/odd pair).
            float other = __shfl_xor_sync(0xffffffffu, prodp, 1);
            if ((lane & 1) == 0) {
                outoc[ph * 32 + (lane >> 1)] = 1.0f - prodp * other;
            }
        }
    }
}

extern "C" void kernel_launch(void* const* d_in, const int* in_sizes, int n_in,
                              void* d_out, int out_size) {
    const float* x   = (const float*)d_in[0];
    const float* wts = (const float*)d_in[1];
    const int*   ci  = (const int*)d_in[2];
    const int*   px  = (const int*)d_in[3];
    const int*   py  = (const int*)d_in[4];
    float*       out = (float*)d_out;

    cudaFuncSetAttribute(logic_tree_kernel,
                         cudaFuncAttributeMaxDynamicSharedMemorySize, SMEM_BYTES);

    prep_kernel<<<16, 256>>>(wts, ci, px, py);

    dim3 grid(16, BATCH);   // 16 spatial tiles x 16 batches = 256 CTAs (one wave at occ 2)
    logic_tree_kernel<<<grid, 256, SMEM_BYTES>>>(x, out);
}

// round 10
// speedup vs baseline: 1.1603x; 1.1603x over previous
#include <cuda_runtime.h>

#define BATCH   16
#define CIN     64
#define HW      64
#define OC      128
#define NLEAF   16
#define NGATE   15

// Spatial y-tile per CTA: 32 wide x 8 tall. Halo for taps (py,px in [0,2], pad 1):
// x rows [r0-1, r0+8] (10 rows), x cols [c0-1, c0+32] (34 cols).
#define TW 32
#define TH 8
#define SC 34
#define SR 10
#define CH_STRIDE (SR * SC)            // 340
#define SMEM_ELEMS (CIN * CH_STRIDE)   // 21760
#define SMEM_BYTES (SMEM_ELEMS * 4)    // 87040

// Precomputed per-launch (deterministic function of inputs; recomputed every replay).
__device__ float g_coef[OC * NGATE * 4];   // per gate: {c0, ca, cb, cab}, 16B-aligned per oc
__device__ int   g_off[OC * NLEAF];

__device__ __constant__ float OP2POLY[16][4] = {
    {0, 0, 0, 0}, {0, 0, 0, 1}, {0, 1, 0, -1}, {0, 1, 0, 0},
    {0, 0, 1, -1}, {0, 0, 1, 0}, {0, 1, 1, -2}, {0, 1, 1, -1},
    {1, -1, -1, 1}, {1, -1, -1, 2}, {1, 0, -1, 0}, {1, 0, -1, 1},
    {1, -1, 0, 0}, {1, -1, 0, 1}, {1, 0, 0, -1}, {1, 0, 0, 0}
};

// Tiny prep: argmax over 16 ops -> 4 poly coeffs per gate; fold (ci,py,px) into a
// single smem element offset per leaf.
__global__ void prep_kernel(const float* __restrict__ w,
                            const int* __restrict__ ci,
                            const int* __restrict__ px,
                            const int* __restrict__ py) {
    int tid = blockIdx.x * blockDim.x + threadIdx.x;
    if (tid < OC * NGATE) {
        const float* wp = w + tid * 16;
        float best = wp[0];
        int bi = 0;
#pragma unroll
        for (int k = 1; k < 16; k++) {
            float v = wp[k];
            if (v > best) { best = v; bi = k; }  // first-max tiebreak == jnp.argmax
        }
#pragma unroll
        for (int c = 0; c < 4; c++) g_coef[tid * 4 + c] = OP2POLY[bi][c];
    }
    if (tid < OC * NLEAF) {
        g_off[tid] = ci[tid] * CH_STRIDE + py[tid] * SC + px[tid];
    }
}

// Horner-form gate: c0 + ca*a + cb*b + cab*a*b = (cab*a + cb)*b + (ca*a + c0)
// 3 FMA total (was mul + 3 FMA).
__device__ __forceinline__ float gate3(float c0, float ca, float cb, float cab,
                                       float a, float b) {
    float t = fmaf(cab, a, cb);
    float s = fmaf(ca, a, c0);
    return fmaf(t, b, s);
}

__global__ void __launch_bounds__(256, 2)
logic_tree_kernel(const float* __restrict__ x, float* __restrict__ out) {
    extern __shared__ float sm[];

    const int tile = blockIdx.x;        // 0..15: tx in [0,2), ty in [0,8)
    const int b    = blockIdx.y;        // 0..15
    const int tx   = tile & 1;
    const int ty   = tile >> 1;
    const int r0   = ty * TH;
    const int c0   = tx * TW;
    const int tid  = threadIdx.x;

    // Stage all 64 channels of the halo region into smem (COALESCED: consecutive
    // threads touch consecutive addresses; zero-fill OOB).
    const float* xb = x + (size_t)b * CIN * HW * HW;
    for (int idx = tid; idx < SMEM_ELEMS; idx += 256) {
        int c   = idx / CH_STRIDE;
        int rem = idx - c * CH_STRIDE;
        int r   = rem / SC;
        int col = rem - r * SC;
        int gr  = r0 - 1 + r;
        int gc  = c0 - 1 + col;
        float v = 0.0f;
        if ((unsigned)gr < HW && (unsigned)gc < HW)
            v = xb[(c * HW + gr) * HW + gc];
        sm[idx] = v;
    }
    __syncthreads();

    const int w    = tid >> 5;   // warp 0..7
    const int lane = tid & 31;   // y-column within tile -> conflict-free LDS

    for (int oc = w; oc < OC; oc += 8) {
        // Leaf smem indices hoisted: lane folded in once; subrow becomes an
        // immediate offset on the LDS below.
        int idx[NLEAF];
        {
            const int4* op = (const int4*)&g_off[oc * NLEAF];
#pragma unroll
            for (int q = 0; q < 4; q++) {
                int4 o4 = op[q];
                idx[4 * q + 0] = o4.x + lane;
                idx[4 * q + 1] = o4.y + lane;
                idx[4 * q + 2] = o4.z + lane;
                idx[4 * q + 3] = o4.w + lane;
            }
        }

        // Coefficients: 15 gates x float4 (vectorized 128-bit loads, warp-uniform).
        float4 cf[NGATE];
        {
            const float4* cp = (const float4*)&g_coef[oc * NGATE * 4];
#pragma unroll
            for (int k = 0; k < NGATE; k++) cf[k] = cp[k];
        }

        float* outoc = out + (((size_t)b * OC + oc) * 32 + ty * 4) * 32 + tx * 16;

#pragma unroll
        for (int ph = 0; ph < 4; ph++) {
            float prodp = 1.0f;
#pragma unroll
            for (int sub = 0; sub < 2; sub++) {
                const int srow = (ph * 2 + sub) * SC;   // compile-time constant

                float v[16];
#pragma unroll
                for (int n = 0; n < 16; n++) v[n] = sm[idx[n] + srow];

                float u[8];
#pragma unroll
                for (int n = 0; n < 8; n++)
                    u[n] = gate3(cf[n].x, cf[n].y, cf[n].z, cf[n].w,
                                 v[2 * n], v[2 * n + 1]);

                float t[4];
#pragma unroll
                for (int n = 0; n < 4; n++)
                    t[n] = gate3(cf[8 + n].x, cf[8 + n].y, cf[8 + n].z, cf[8 + n].w,
                                 u[2 * n], u[2 * n + 1]);

                float s0 = gate3(cf[12].x, cf[12].y, cf[12].z, cf[12].w, t[0], t[1]);
                float s1 = gate3(cf[13].x, cf[13].y, cf[13].z, cf[13].w, t[2], t[3]);
                float y  = gate3(cf[14].x, cf[14].y, cf[14].z, cf[14].w, s0, s1);

                // prodp *= (1 - y)  as a single FMA
                prodp = fmaf(-prodp, y, prodp);
            }
            // Column pooling: combine neighbor lane (j even/odd pair).
            float other = __shfl_xor_sync(0xffffffffu, prodp, 1);
            if ((lane & 1) == 0) {
                outoc[ph * 32 + (lane >> 1)] = 1.0f - prodp * other;
            }
        }
    }
}

extern "C" void kernel_launch(void* const* d_in, const int* in_sizes, int n_in,
                              void* d_out, int out_size) {
    const float* x   = (const float*)d_in[0];
    const float* wts = (const float*)d_in[1];
    const int*   ci  = (const int*)d_in[2];
    const int*   px  = (const int*)d_in[3];
    const int*   py  = (const int*)d_in[4];
    float*       out = (float*)d_out;

    cudaFuncSetAttribute(logic_tree_kernel,
                         cudaFuncAttributeMaxDynamicSharedMemorySize, SMEM_BYTES);

    prep_kernel<<<16, 256>>>(wts, ci, px, py);

    dim3 grid(16, BATCH);   // 16 spatial tiles x 16 batches = 256 CTAs (one wave at occ 2)
    logic_tree_kernel<<<grid, 256, SMEM_BYTES>>>(x, out);
}